// round 5
// baseline (speedup 1.0000x reference)
#include <cuda_runtime.h>
#include <math.h>

#define E    4096
#define H    32
#define D    128
#define PAST 8191
#define KTOT 8192
#define NCHUNK 512
#define CHUNK  16

#define NSEG  128   // row segments for big GEMVs (32 rows each)

// ---- device scratch (no allocations allowed) ----
__device__ float g_q[E];                        // query (biased)
__device__ float g_kv[2 * D];                   // [key_new | value_new]
__device__ float g_part[(size_t)NSEG * E];      // GEMV partials (2 MB)
__device__ float g_m[NCHUNK * H];
__device__ float g_l[NCHUNK * H];
__device__ float g_po[(size_t)NCHUNK * H * D];  // 8 MB
__device__ float g_attn[E];

// ---------------------------------------------------------------------------
__global__ void init_kernel(const float* __restrict__ qb,
                            const float* __restrict__ kvb) {
    int t = blockIdx.x * blockDim.x + threadIdx.x;
    if (t < E) g_q[t] = qb[t];
    if (t < 2 * D) g_kv[t] = kvb[t];
}

// ---------------------------------------------------------------------------
// GEMV partial: part[seg][j] = sum_{i in seg} x[i] * W[i*ncols + j]
// grid = (ncols/1024, NSEG), 256 threads. Plain stores, no contention.
// ---------------------------------------------------------------------------
__global__ void gemv_part(const float* __restrict__ x,
                          const float* __restrict__ W,
                          float* __restrict__ part,
                          int ncols) {
    __shared__ float xs[32];
    const int i0 = blockIdx.y * 32;
    if (threadIdx.x < 32) xs[threadIdx.x] = x[i0 + threadIdx.x];
    __syncthreads();

    int j = blockIdx.x * 1024 + threadIdx.x * 4;
    if (j >= ncols) return;

    const float* wp = W + (size_t)i0 * ncols + j;
    float a0 = 0.f, a1 = 0.f, a2 = 0.f, a3 = 0.f;
#pragma unroll 8
    for (int i = 0; i < 32; i++) {
        float4 w = __ldg((const float4*)(wp + (size_t)i * ncols));
        float xv = xs[i];
        a0 += xv * w.x; a1 += xv * w.y; a2 += xv * w.z; a3 += xv * w.w;
    }
    float4 r = make_float4(a0, a1, a2, a3);
    *(float4*)&part[(size_t)blockIdx.y * ncols + j] = r;
}

// ---------------------------------------------------------------------------
// Reduce partials: out[j] += sum_s part[s][j]. grid (ncols/1024, 4), 256 thr.
// out must be pre-seeded with the bias. Only 4-way atomic conflict.
// ---------------------------------------------------------------------------
__global__ void reduce_add(const float* __restrict__ part,
                           float* __restrict__ out,
                           int ncols) {
    int j = blockIdx.x * 1024 + threadIdx.x * 4;
    if (j >= ncols) return;
    const int s0 = blockIdx.y * (NSEG / 4);
    float a0 = 0.f, a1 = 0.f, a2 = 0.f, a3 = 0.f;
#pragma unroll 8
    for (int s = 0; s < NSEG / 4; s++) {
        float4 p = __ldg((const float4*)&part[(size_t)(s0 + s) * ncols + j]);
        a0 += p.x; a1 += p.y; a2 += p.z; a3 += p.w;
    }
    atomicAdd(&out[j + 0], a0);
    atomicAdd(&out[j + 1], a1);
    atomicAdd(&out[j + 2], a2);
    atomicAdd(&out[j + 3], a3);
}

// ---------------------------------------------------------------------------
// Small GEMV for kv (ncols=256): atomic version, low conflict volume.
// grid = (1, NSEG), 256 threads: thread j owns one column.
// ---------------------------------------------------------------------------
__global__ void gemv_kv(const float* __restrict__ x,
                        const float* __restrict__ W,
                        float* __restrict__ out) {
    __shared__ float xs[32];
    const int i0 = blockIdx.y * 32;
    if (threadIdx.x < 32) xs[threadIdx.x] = x[i0 + threadIdx.x];
    __syncthreads();
    const int j = threadIdx.x;           // 0..255
    float a = 0.f;
#pragma unroll 8
    for (int i = 0; i < 32; i++)
        a += xs[i] * __ldg(&W[(size_t)(i0 + i) * 256 + j]);
    atomicAdd(&out[j], a);
}

// ---------------------------------------------------------------------------
// Split-K attention partial: 512 blocks x 128 threads, 16 keys per block.
// K/V streamed from GMEM; q + scores in smem.
// ---------------------------------------------------------------------------
__global__ void __launch_bounds__(128)
attn_partial(const float* __restrict__ pk,   // (D, PAST) d-major
             const float* __restrict__ pv,   // (PAST, D) k-major
             const float* __restrict__ mask) // (KTOT)
{
    __shared__ float qs[E];          // scaled q (h*D + d)  16 KB
    __shared__ float ss[H * CHUNK];  // scores -> weights    2 KB

    const int t = threadIdx.x;
    const int kbase = blockIdx.x * CHUNK;
    const float scale = 0.088388347648318447f; // 1/sqrt(128)

#pragma unroll
    for (int i = t * 4; i < E; i += 128 * 4) {
        float4 v = *(const float4*)&g_q[i];
        v.x *= scale; v.y *= scale; v.z *= scale; v.w *= scale;
        *(float4*)&qs[i] = v;
    }
    __syncthreads();

    // ---- score phase: key = t&15, group g = t>>4 owns 4 heads ----
    {
        const int kk = t & 15;
        const int g  = t >> 4;           // 0..7
        const int kg = kbase + kk;

        const float* kp; int kstr;
        if (kg < PAST) { kp = pk + kg; kstr = PAST; }
        else           { kp = g_kv;   kstr = 1;    }

        float a0 = 0.f, a1 = 0.f, a2 = 0.f, a3 = 0.f;
#pragma unroll 8
        for (int d4 = 0; d4 < D / 4; d4++) {
            const int d = d4 * 4;
            float k0 = kp[(size_t)(d + 0) * kstr];
            float k1 = kp[(size_t)(d + 1) * kstr];
            float k2 = kp[(size_t)(d + 2) * kstr];
            float k3 = kp[(size_t)(d + 3) * kstr];
            float4 q0 = *(const float4*)&qs[(g * 4 + 0) * D + d];
            float4 q1 = *(const float4*)&qs[(g * 4 + 1) * D + d];
            float4 q2 = *(const float4*)&qs[(g * 4 + 2) * D + d];
            float4 q3 = *(const float4*)&qs[(g * 4 + 3) * D + d];
            a0 += q0.x * k0 + q0.y * k1 + q0.z * k2 + q0.w * k3;
            a1 += q1.x * k0 + q1.y * k1 + q1.z * k2 + q1.w * k3;
            a2 += q2.x * k0 + q2.y * k1 + q2.z * k2 + q2.w * k3;
            a3 += q3.x * k0 + q3.y * k1 + q3.z * k2 + q3.w * k3;
        }
        float mk = mask[kg];
        ss[(g * 4 + 0) * CHUNK + kk] = a0 + mk;
        ss[(g * 4 + 1) * CHUNK + kk] = a1 + mk;
        ss[(g * 4 + 2) * CHUNK + kk] = a2 + mk;
        ss[(g * 4 + 3) * CHUNK + kk] = a3 + mk;
    }
    __syncthreads();

    // ---- softmax: 4 threads per head, 4 keys each, shuffle reduce ----
    {
        const int h = t >> 2;          // 0..31
        const int j = (t & 3) * 4;
        float4 s = *(const float4*)&ss[h * CHUNK + j];
        float m = fmaxf(fmaxf(s.x, s.y), fmaxf(s.z, s.w));
        m = fmaxf(m, __shfl_xor_sync(0xffffffff, m, 1));
        m = fmaxf(m, __shfl_xor_sync(0xffffffff, m, 2));
        s.x = __expf(s.x - m); s.y = __expf(s.y - m);
        s.z = __expf(s.z - m); s.w = __expf(s.w - m);
        float l = s.x + s.y + s.z + s.w;
        l += __shfl_xor_sync(0xffffffff, l, 1);
        l += __shfl_xor_sync(0xffffffff, l, 2);
        *(float4*)&ss[h * CHUNK + j] = s;
        if ((t & 3) == 0) {
            g_m[blockIdx.x * H + h] = m;
            g_l[blockIdx.x * H + h] = l;
        }
    }
    __syncthreads();

    // ---- AV phase: thread = d (0..127), 32 head accumulators ----
    {
        float o[H];
#pragma unroll
        for (int h = 0; h < H; h++) o[h] = 0.f;

#pragma unroll
        for (int k4 = 0; k4 < CHUNK / 4; k4++) {
            const int k = k4 * 4;
            const int kg0 = kbase + k;
            const float* v0p = (kg0 + 0 < PAST) ? pv + (size_t)(kg0 + 0) * D : g_kv + D;
            const float* v1p = (kg0 + 1 < PAST) ? pv + (size_t)(kg0 + 1) * D : g_kv + D;
            const float* v2p = (kg0 + 2 < PAST) ? pv + (size_t)(kg0 + 2) * D : g_kv + D;
            const float* v3p = (kg0 + 3 < PAST) ? pv + (size_t)(kg0 + 3) * D : g_kv + D;
            float v0 = v0p[t];
            float v1 = v1p[t];
            float v2 = v2p[t];
            float v3 = v3p[t];
#pragma unroll
            for (int h = 0; h < H; h++) {
                float4 wv = *(const float4*)&ss[h * CHUNK + k];
                o[h] += wv.x * v0 + wv.y * v1 + wv.z * v2 + wv.w * v3;
            }
        }
#pragma unroll
        for (int h = 0; h < H; h++)
            g_po[((size_t)blockIdx.x * H + h) * D + t] = o[h];
    }
}

// ---------------------------------------------------------------------------
// Combine partials (blocks 0..31 = heads, 128 threads = d).
// Block 32: seed d_out with proj bias + write key_perm / value_new tail.
// ---------------------------------------------------------------------------
__global__ void combine_kernel(const float* __restrict__ proj_b,
                               float* __restrict__ out) {
    if (blockIdx.x == H) {
        for (int j = threadIdx.x; j < E; j += blockDim.x) out[j] = proj_b[j];
        if (threadIdx.x < D) {
            out[E + threadIdx.x]     = g_kv[threadIdx.x];       // key_perm
            out[E + D + threadIdx.x] = g_kv[D + threadIdx.x];   // value_new
        }
        return;
    }
    const int h = blockIdx.x;
    const int d = threadIdx.x;

    float m = -1e30f;
#pragma unroll 16
    for (int c = 0; c < NCHUNK; c++) m = fmaxf(m, g_m[c * H + h]);

    float L = 0.f, o = 0.f;
#pragma unroll 8
    for (int c = 0; c < NCHUNK; c++) {
        float sc = __expf(g_m[c * H + h] - m);
        L += g_l[c * H + h] * sc;
        o += __ldg(&g_po[((size_t)c * H + h) * D + d]) * sc;
    }
    g_attn[h * D + d] = o / L;
}

// ---------------------------------------------------------------------------
extern "C" void kernel_launch(void* const* d_in, const int* in_sizes, int n_in,
                              void* d_out, int out_size) {
    const float* hs   = (const float*)d_in[0];
    const float* pk   = (const float*)d_in[1];
    const float* pv   = (const float*)d_in[2];
    const float* mask = (const float*)d_in[3];
    const float* qw   = (const float*)d_in[4];
    const float* qb   = (const float*)d_in[5];
    const float* kvw  = (const float*)d_in[6];
    const float* kvb  = (const float*)d_in[7];
    const float* pw   = (const float*)d_in[8];
    const float* pb   = (const float*)d_in[9];
    float* out = (float*)d_out;

    float *gq = nullptr, *gkv = nullptr, *gattn = nullptr, *gpart = nullptr;
    cudaGetSymbolAddress((void**)&gq,    g_q);
    cudaGetSymbolAddress((void**)&gkv,   g_kv);
    cudaGetSymbolAddress((void**)&gattn, g_attn);
    cudaGetSymbolAddress((void**)&gpart, g_part);

    // 1) seed biases (resets accumulators every replay)
    init_kernel<<<16, 256>>>(qb, kvb);

    // 2) q = h @ q_w + q_b : partials then reduce into bias-seeded g_q
    gemv_part<<<dim3(4, NSEG), 256>>>(hs, qw, gpart, E);
    reduce_add<<<dim3(4, 4), 256>>>(gpart, gq, E);

    // 3) kv = h @ kv_w + kv_b (small, atomic)
    gemv_kv<<<dim3(1, NSEG), 256>>>(hs, kvw, gkv);

    // 4) split-K attention partials (512 chunks of 16 keys)
    attn_partial<<<NCHUNK, 128>>>(pk, pv, mask);

    // 5) merge partials; seed output with proj bias; write kv outputs
    combine_kernel<<<H + 1, 128>>>(pb, out);

    // 6) out[0:4096] += attn @ proj_w : partials then reduce
    gemv_part<<<dim3(4, NSEG), 256>>>(gattn, pw, gpart, E);
    reduce_add<<<dim3(4, 4), 256>>>(gpart, out, E);
}

// round 6
// speedup vs baseline: 1.4612x; 1.4612x over previous
#include <cuda_runtime.h>
#include <math.h>

#define E    4096
#define H    32
#define D    128
#define PAST 8191
#define KTOT 8192
#define NCHUNK 256
#define CHUNK  32

// ---- device scratch (no allocations allowed) ----
__device__ float g_q[E];                        // query (biased)
__device__ float g_kv[2 * D];                   // [key_new | value_new]
__device__ float g_m[NCHUNK * H];
__device__ float g_l[NCHUNK * H];
__device__ float g_po[(size_t)NCHUNK * H * D];  // 4 MB
__device__ float g_attn[E];

// ---------------------------------------------------------------------------
__global__ void init_kernel(const float* __restrict__ qb,
                            const float* __restrict__ kvb) {
    int t = blockIdx.x * blockDim.x + threadIdx.x;
    if (t < E) g_q[t] = qb[t];
    if (t < 2 * D) g_kv[t] = kvb[t];
}

__global__ void nop_kernel() {}

// ---------------------------------------------------------------------------
// Fused q+kv GEMV. grid (5, 128), 256 threads.
//   x < 4 : q path, 1024 cols per block (R2-proven form)
//   x == 4: kv path, 256 cols (64 active threads), rides under the q stream
// ---------------------------------------------------------------------------
__global__ void gemv_fused(const float* __restrict__ x,
                           const float* __restrict__ Wq,
                           const float* __restrict__ Wkv) {
    __shared__ float xs[32];
    const int i0 = blockIdx.y * 32;
    if (threadIdx.x < 32) xs[threadIdx.x] = x[i0 + threadIdx.x];
    __syncthreads();

    if (blockIdx.x < 4) {
        const int j = blockIdx.x * 1024 + threadIdx.x * 4;
        const float* wp = Wq + (size_t)i0 * E + j;
        float a0 = 0.f, a1 = 0.f, a2 = 0.f, a3 = 0.f;
#pragma unroll 8
        for (int i = 0; i < 32; i++) {
            float4 w = __ldg((const float4*)(wp + (size_t)i * E));
            float xv = xs[i];
            a0 += xv * w.x; a1 += xv * w.y; a2 += xv * w.z; a3 += xv * w.w;
        }
        atomicAdd(&g_q[j + 0], a0);
        atomicAdd(&g_q[j + 1], a1);
        atomicAdd(&g_q[j + 2], a2);
        atomicAdd(&g_q[j + 3], a3);
    } else {
        if (threadIdx.x >= 64) return;
        const int j = threadIdx.x * 4;
        const float* wp = Wkv + (size_t)i0 * 256 + j;
        float a0 = 0.f, a1 = 0.f, a2 = 0.f, a3 = 0.f;
#pragma unroll 8
        for (int i = 0; i < 32; i++) {
            float4 w = __ldg((const float4*)(wp + (size_t)i * 256));
            float xv = xs[i];
            a0 += xv * w.x; a1 += xv * w.y; a2 += xv * w.z; a3 += xv * w.w;
        }
        atomicAdd(&g_kv[j + 0], a0);
        atomicAdd(&g_kv[j + 1], a1);
        atomicAdd(&g_kv[j + 2], a2);
        atomicAdd(&g_kv[j + 3], a3);
    }
}

// ---------------------------------------------------------------------------
// Plain GEMV (R2 form) for the output projection. grid (4,128), 256 threads.
// out must be pre-seeded with proj bias (combine does it).
// ---------------------------------------------------------------------------
__global__ void gemv_atomic(const float* __restrict__ x,
                            const float* __restrict__ W,
                            float* __restrict__ out,
                            int ncols) {
    __shared__ float xs[32];
    const int i0 = blockIdx.y * 32;
    if (threadIdx.x < 32) xs[threadIdx.x] = x[i0 + threadIdx.x];
    __syncthreads();

    const int j = blockIdx.x * 1024 + threadIdx.x * 4;
    if (j >= ncols) return;

    const float* wp = W + (size_t)i0 * ncols + j;
    float a0 = 0.f, a1 = 0.f, a2 = 0.f, a3 = 0.f;
#pragma unroll 8
    for (int i = 0; i < 32; i++) {
        float4 w = __ldg((const float4*)(wp + (size_t)i * ncols));
        float xv = xs[i];
        a0 += xv * w.x; a1 += xv * w.y; a2 += xv * w.z; a3 += xv * w.w;
    }
    atomicAdd(&out[j + 0], a0);
    atomicAdd(&out[j + 1], a1);
    atomicAdd(&out[j + 2], a2);
    atomicAdd(&out[j + 3], a3);
}

// ---------------------------------------------------------------------------
// Split-K attention partial (R4 form, measured 21.2us): 256 blocks x 128 thr,
// 32 keys per block. K/V streamed from GMEM; q + scores in smem.
// ---------------------------------------------------------------------------
__global__ void __launch_bounds__(128)
attn_partial(const float* __restrict__ pk,   // (D, PAST) d-major
             const float* __restrict__ pv,   // (PAST, D) k-major
             const float* __restrict__ mask) // (KTOT)
{
    __shared__ float qs[E];          // scaled q (h*D + d)  16 KB
    __shared__ float ss[H * CHUNK];  // scores -> weights    4 KB

    const int t = threadIdx.x;
    const int kbase = blockIdx.x * CHUNK;
    const float scale = 0.088388347648318447f; // 1/sqrt(128)

#pragma unroll
    for (int i = t * 4; i < E; i += 128 * 4) {
        float4 v = *(const float4*)&g_q[i];
        v.x *= scale; v.y *= scale; v.z *= scale; v.w *= scale;
        *(float4*)&qs[i] = v;
    }
    __syncthreads();

    // ---- score phase: lane = key, warp w owns heads w*8..w*8+7 ----
    {
        const int lane = t & 31;
        const int w = t >> 5;
        const int kg = kbase + lane;

        const float* kp; int kstr;
        if (kg < PAST) { kp = pk + kg; kstr = PAST; }
        else           { kp = g_kv;   kstr = 1;    }

        float acc[8];
#pragma unroll
        for (int h = 0; h < 8; h++) acc[h] = 0.f;

#pragma unroll 8
        for (int d4 = 0; d4 < D / 4; d4++) {
            const int d = d4 * 4;
            float k0 = __ldg(&kp[(size_t)(d + 0) * kstr]);
            float k1 = __ldg(&kp[(size_t)(d + 1) * kstr]);
            float k2 = __ldg(&kp[(size_t)(d + 2) * kstr]);
            float k3 = __ldg(&kp[(size_t)(d + 3) * kstr]);
#pragma unroll
            for (int h = 0; h < 8; h++) {
                float4 qv = *(const float4*)&qs[(w * 8 + h) * D + d];
                acc[h] += qv.x * k0 + qv.y * k1 + qv.z * k2 + qv.w * k3;
            }
        }
        float mk = __ldg(&mask[kg]);
#pragma unroll
        for (int h = 0; h < 8; h++) ss[(w * 8 + h) * CHUNK + lane] = acc[h] + mk;
    }
    __syncthreads();

    // ---- softmax: 4 threads per head (8 keys each), shuffle reduce ----
    {
        const int h = t >> 2;
        const int j = (t & 3) * 8;
        float4 s0 = *(const float4*)&ss[h * CHUNK + j];
        float4 s1 = *(const float4*)&ss[h * CHUNK + j + 4];
        float m = fmaxf(fmaxf(fmaxf(s0.x, s0.y), fmaxf(s0.z, s0.w)),
                        fmaxf(fmaxf(s1.x, s1.y), fmaxf(s1.z, s1.w)));
        m = fmaxf(m, __shfl_xor_sync(0xffffffff, m, 1));
        m = fmaxf(m, __shfl_xor_sync(0xffffffff, m, 2));
        s0.x = __expf(s0.x - m); s0.y = __expf(s0.y - m);
        s0.z = __expf(s0.z - m); s0.w = __expf(s0.w - m);
        s1.x = __expf(s1.x - m); s1.y = __expf(s1.y - m);
        s1.z = __expf(s1.z - m); s1.w = __expf(s1.w - m);
        float l = s0.x + s0.y + s0.z + s0.w + s1.x + s1.y + s1.z + s1.w;
        l += __shfl_xor_sync(0xffffffff, l, 1);
        l += __shfl_xor_sync(0xffffffff, l, 2);
        *(float4*)&ss[h * CHUNK + j]     = s0;
        *(float4*)&ss[h * CHUNK + j + 4] = s1;
        if ((t & 3) == 0) {
            g_m[blockIdx.x * H + h] = m;
            g_l[blockIdx.x * H + h] = l;
        }
    }
    __syncthreads();

    // ---- AV phase: thread = d (0..127), 32 head accumulators ----
    {
        float o[H];
#pragma unroll
        for (int h = 0; h < H; h++) o[h] = 0.f;

#pragma unroll 2
        for (int k4 = 0; k4 < CHUNK / 4; k4++) {
            const int k = k4 * 4;
            const int kg0 = kbase + k;
            const float* v0p = (kg0 + 0 < PAST) ? pv + (size_t)(kg0 + 0) * D : g_kv + D;
            const float* v1p = (kg0 + 1 < PAST) ? pv + (size_t)(kg0 + 1) * D : g_kv + D;
            const float* v2p = (kg0 + 2 < PAST) ? pv + (size_t)(kg0 + 2) * D : g_kv + D;
            const float* v3p = (kg0 + 3 < PAST) ? pv + (size_t)(kg0 + 3) * D : g_kv + D;
            float v0 = __ldg(&v0p[t]);
            float v1 = __ldg(&v1p[t]);
            float v2 = __ldg(&v2p[t]);
            float v3 = __ldg(&v3p[t]);
#pragma unroll
            for (int h = 0; h < H; h++) {
                float4 wv = *(const float4*)&ss[h * CHUNK + k];
                o[h] += wv.x * v0 + wv.y * v1 + wv.z * v2 + wv.w * v3;
            }
        }
#pragma unroll
        for (int h = 0; h < H; h++)
            g_po[((size_t)blockIdx.x * H + h) * D + t] = o[h];
    }
}

// ---------------------------------------------------------------------------
// Combine v2: grid 65 blocks, 256 threads.
// Blocks 0..63: (h = b>>1, dhalf = b&1). Cooperative m/L; chunk-split o sums.
// Block 64: seed d_out with proj bias + key_perm/value_new tail.
// ---------------------------------------------------------------------------
__global__ void combine_kernel(const float* __restrict__ proj_b,
                               float* __restrict__ out) {
    if (blockIdx.x == 64) {
        for (int j = threadIdx.x; j < E; j += blockDim.x) out[j] = proj_b[j];
        if (threadIdx.x < D) {
            out[E + threadIdx.x]     = g_kv[threadIdx.x];       // key_perm
            out[E + D + threadIdx.x] = g_kv[D + threadIdx.x];   // value_new
        }
        return;
    }
    const int h    = blockIdx.x >> 1;
    const int half = blockIdx.x & 1;
    const int t    = threadIdx.x;

    __shared__ float red[256];
    __shared__ float sc[NCHUNK];

    // max over 256 chunks (one per thread)
    float mv = g_m[t * H + h];
    red[t] = mv;
    __syncthreads();
#pragma unroll
    for (int s = 128; s > 0; s >>= 1) {
        if (t < s) red[t] = fmaxf(red[t], red[t + s]);
        __syncthreads();
    }
    const float m = red[0];
    __syncthreads();

    float e = __expf(mv - m);
    sc[t] = e;
    red[t] = e * g_l[t * H + h];
    __syncthreads();
#pragma unroll
    for (int s = 128; s > 0; s >>= 1) {
        if (t < s) red[t] += red[t + s];
        __syncthreads();
    }
    const float L = red[0];
    __syncthreads();

    // o: thread (d = half*64 + t&63, quarter = t>>6 over chunks)
    const int d = half * 64 + (t & 63);
    const int q = t >> 6;
    float o = 0.f;
#pragma unroll 8
    for (int c = q * 64; c < q * 64 + 64; c++)
        o += __ldg(&g_po[((size_t)c * H + h) * D + d]) * sc[c];
    red[t] = o;
    __syncthreads();
    if (t < 64) {
        float oo = red[t] + red[t + 64] + red[t + 128] + red[t + 192];
        g_attn[h * D + half * 64 + t] = oo / L;
    }
}

// ---------------------------------------------------------------------------
extern "C" void kernel_launch(void* const* d_in, const int* in_sizes, int n_in,
                              void* d_out, int out_size) {
    const float* hs   = (const float*)d_in[0];
    const float* pk   = (const float*)d_in[1];
    const float* pv   = (const float*)d_in[2];
    const float* mask = (const float*)d_in[3];
    const float* qw   = (const float*)d_in[4];
    const float* qb   = (const float*)d_in[5];
    const float* kvw  = (const float*)d_in[6];
    const float* kvb  = (const float*)d_in[7];
    const float* pw   = (const float*)d_in[8];
    const float* pb   = (const float*)d_in[9];
    float* out = (float*)d_out;

    float *gattn = nullptr;
    cudaGetSymbolAddress((void**)&gattn, g_attn);

    // 1) seed biases (resets atomic accumulators every replay)
    init_kernel<<<16, 256>>>(qb, kvb);

    // 2,3) no-ops so the profiled launch (#4) is the big GEMV
    nop_kernel<<<1, 32>>>();
    nop_kernel<<<1, 32>>>();

    // 4) q + kv GEMV fused  <-- PROFILED LAUNCH
    gemv_fused<<<dim3(5, 128), 256>>>(hs, qw, kvw);

    // 5) split-K attention partials (256 chunks of 32 keys)
    attn_partial<<<NCHUNK, 128>>>(pk, pv, mask);

    // 6) merge partials; seed output with proj bias; write kv tail
    combine_kernel<<<65, 256>>>(pb, out);

    // 7) out[0:4096] += attn @ proj_w
    gemv_atomic<<<dim3(4, 128), 256>>>(gattn, pw, out, E);
}